// round 9
// baseline (speedup 1.0000x reference)
#include <cuda_runtime.h>

#define B_ 16
#define N_ 2048
#define D_ 256
#define H_ 64
#define R_ 62            // output rows per tile
#define AR 64            // A rows incl. 2 halo rows
#define NT 34            // ceil(N_/R_)
#define CH 128           // m-chunk columns
#define NCH 16           // N_/CH
#define AS 132           // col stride for a/e/kt (pad)
#define QS 68            // qt row stride (pad)
#define SCALE 0.125f     // H^-0.5

__device__ float g_q[B_*N_*H_];
__device__ float g_k[B_*N_*H_];
__device__ float g_v[B_*N_*H_];

// ---------------------------------------------------------------------------
// Kernel 1: QKV projection.  out[b,n,h] = x[b,n,:] @ W[:,h] + bias[h]
// grid = (512, 3): 64 rows per CTA, blockIdx.y selects {q,k,v}
// ---------------------------------------------------------------------------
__global__ __launch_bounds__(256) void qkv_kernel_75625784(
    const float* __restrict__ x,
    const float* __restrict__ Wq, const float* __restrict__ bq,
    const float* __restrict__ Wk, const float* __restrict__ bk,
    const float* __restrict__ Wv, const float* __restrict__ bv)
{
    __shared__ float xs[64*64];
    __shared__ float ws[64*64];
    const int mat = blockIdx.y;
    const float* W    = (mat==0) ? Wq : (mat==1 ? Wk : Wv);
    const float* bias = (mat==0) ? bq : (mat==1 ? bk : bv);
    float* outg       = (mat==0) ? g_q : (mat==1 ? g_k : g_v);
    const int row0 = blockIdx.x * 64;
    const int tid = threadIdx.x;
    const int rt = tid >> 4;
    const int ht = tid & 15;

    float acc[4][4];
    #pragma unroll
    for (int i = 0; i < 4; ++i)
        #pragma unroll
        for (int j = 0; j < 4; ++j) acc[i][j] = 0.f;

    for (int dc = 0; dc < D_; dc += 64) {
        #pragma unroll
        for (int it = 0; it < 4; ++it) {
            int fi = it*256 + tid;
            int r = fi >> 4, c4 = fi & 15;
            *(float4*)&xs[r*64 + c4*4] =
                *(const float4*)&x[(size_t)(row0 + r)*D_ + dc + c4*4];
            *(float4*)&ws[r*64 + c4*4] =
                *(const float4*)&W[(size_t)(dc + r)*H_ + c4*4];
        }
        __syncthreads();
        #pragma unroll
        for (int d4 = 0; d4 < 16; ++d4) {
            float av[4][4], bv4[4][4];
            #pragma unroll
            for (int i = 0; i < 4; ++i) {
                float4 t = *(const float4*)&xs[(rt*4+i)*64 + d4*4];
                av[i][0]=t.x; av[i][1]=t.y; av[i][2]=t.z; av[i][3]=t.w;
            }
            #pragma unroll
            for (int u = 0; u < 4; ++u) {
                float4 t = *(const float4*)&ws[(d4*4+u)*64 + ht*4];
                bv4[u][0]=t.x; bv4[u][1]=t.y; bv4[u][2]=t.z; bv4[u][3]=t.w;
            }
            #pragma unroll
            for (int i = 0; i < 4; ++i)
                #pragma unroll
                for (int j = 0; j < 4; ++j)
                    acc[i][j] += av[i][0]*bv4[0][j] + av[i][1]*bv4[1][j]
                               + av[i][2]*bv4[2][j] + av[i][3]*bv4[3][j];
        }
        __syncthreads();
    }
    float4 bb = *(const float4*)&bias[ht*4];
    #pragma unroll
    for (int i = 0; i < 4; ++i) {
        float4 r;
        r.x = acc[i][0] + bb.x; r.y = acc[i][1] + bb.y;
        r.z = acc[i][2] + bb.z; r.w = acc[i][3] + bb.w;
        *(float4*)&outg[(size_t)(row0 + rt*4 + i)*H_ + ht*4] = r;
    }
}

// ---------------------------------------------------------------------------
// Kernel 2: streaming fused attention, 512 threads, 64-row tile, 128-col chunks
// ---------------------------------------------------------------------------
__global__ __launch_bounds__(512, 1) void attn2_kernel_75625784(
    const float* __restrict__ conv_w, const float* __restrict__ conv_b,
    float* __restrict__ out)
{
    extern __shared__ float sm[];
    float* a      = sm;                    // [AR][AS]  A chunk (cols 0..127 used)
    float* e      = a  + AR*AS;            // [AR][AS]  e = expm1(relu(...))
    float* kt     = e  + AR*AS;            // [H_][AS]  k^T chunk; cols 128,129 = halo m-1, m+CH
    float* qt     = kt + H_*AS;            // [AR][QS]
    float* vt     = qt + AR*QS;            // [CH][H_]
    float* aLR    = vt + CH*H_;            // [2][AR]   A halo cols (left, right)
    float* rowsum = aLR + 2*AR;            // [AR]
    float* cw     = rowsum + AR;           // [10]

    const int b   = blockIdx.y;
    const int r0  = blockIdx.x * R_;
    const int tid = threadIdx.x;

    if (tid < AR) rowsum[tid] = 0.f;
    if (tid >= 64 && tid < 73) cw[tid-64] = conv_w[tid-64];
    if (tid == 73) cw[9] = conv_b[0];

    // qt: rows r (a-row space), global row gr = r0-1+r; OOB rows -> 0
    #pragma unroll
    for (int it = 0; it < 2; ++it) {
        int idx = tid + it*512;
        int r = idx >> 4, h4 = idx & 15;
        int gr = r0 - 1 + r;
        float4 v = make_float4(0.f, 0.f, 0.f, 0.f);
        if (gr >= 0 && gr < N_)
            v = *(const float4*)&g_q[((size_t)b*N_ + gr)*H_ + h4*4];
        *(float4*)&qt[r*QS + h4*4] = v;
    }
    // e halo rows (0 and 63) are permanently zero
    if (tid < CH) { e[tid] = 0.f; e[63*AS + tid] = 0.f; }
    __syncthreads();

    // thread roles
    const int g   = tid >> 8;            // PV m-half
    const int prg = (tid >> 4) & 15;     // PV row group
    const int phg = tid & 15;            // PV h group
    const int qrg = tid >> 5;            // QK row group (0..15)
    const int qcg = tid & 31;            // QK col group (0..31)
    const int khh = tid & 63;            // kt loader: h
    const int kmg = tid >> 6;            // kt loader: m group (0..7)

    float pv[4][4];
    #pragma unroll
    for (int i = 0; i < 4; ++i)
        #pragma unroll
        for (int j = 0; j < 4; ++j) pv[i][j] = 0.f;

    const float* kb = g_k + (size_t)b*N_*H_;
    const float* vb = g_v + (size_t)b*N_*H_;

    for (int ch = 0; ch < NCH; ++ch) {
        const int mb = ch*CH;

        // ---- load k^T chunk (coalesced gather, 4-way STS conflict tolerated) ----
        #pragma unroll
        for (int it = 0; it < 4; ++it) {
            int m0 = kmg*4 + it*32;
            float4 v;
            v.x = kb[(mb+m0+0)*H_ + khh];
            v.y = kb[(mb+m0+1)*H_ + khh];
            v.z = kb[(mb+m0+2)*H_ + khh];
            v.w = kb[(mb+m0+3)*H_ + khh];
            *(float4*)&kt[khh*AS + m0] = v;
        }
        if (tid < 128) {            // halo k columns (m = mb-1 at 128, m = mb+CH at 129)
            int side = tid >> 6;
            int hh = tid & 63;
            int m = side ? (mb + CH) : (mb - 1);
            kt[hh*AS + CH + side] = (m >= 0 && m < N_) ? kb[m*H_ + hh] : 0.f;
        }
        // ---- load v chunk (coalesced) ----
        #pragma unroll
        for (int it = 0; it < 4; ++it) {
            int idx = tid + it*512;
            int mi = idx >> 4, h4 = idx & 15;
            *(float4*)&vt[mi*H_ + h4*4] =
                *(const float4*)&vb[(size_t)(mb+mi)*H_ + h4*4];
        }
        __syncthreads();

        // ---- QK main: a[r][c] = SCALE * q_r . k_{mb+c}, 64x128, 4x4 tiles ----
        {
            float acc[4][4];
            #pragma unroll
            for (int i = 0; i < 4; ++i)
                #pragma unroll
                for (int j = 0; j < 4; ++j) acc[i][j] = 0.f;
            #pragma unroll
            for (int k4 = 0; k4 < 16; ++k4) {
                float av[4][4], bv4[4][4];
                #pragma unroll
                for (int i = 0; i < 4; ++i) {
                    float4 t = *(const float4*)&qt[(qrg*4+i)*QS + k4*4];
                    av[i][0]=t.x; av[i][1]=t.y; av[i][2]=t.z; av[i][3]=t.w;
                }
                #pragma unroll
                for (int u = 0; u < 4; ++u) {
                    float4 t = *(const float4*)&kt[(k4*4+u)*AS + qcg*4];
                    bv4[u][0]=t.x; bv4[u][1]=t.y; bv4[u][2]=t.z; bv4[u][3]=t.w;
                }
                #pragma unroll
                for (int i = 0; i < 4; ++i)
                    #pragma unroll
                    for (int j = 0; j < 4; ++j)
                        acc[i][j] += av[i][0]*bv4[0][j] + av[i][1]*bv4[1][j]
                                   + av[i][2]*bv4[2][j] + av[i][3]*bv4[3][j];
            }
            #pragma unroll
            for (int i = 0; i < 4; ++i) {
                float4 r;
                r.x = acc[i][0]*SCALE; r.y = acc[i][1]*SCALE;
                r.z = acc[i][2]*SCALE; r.w = acc[i][3]*SCALE;
                *(float4*)&a[(qrg*4+i)*AS + qcg*4] = r;
            }
        }
        // ---- QK halo columns -> aLR ----
        if (tid < 128) {
            int r = tid >> 1, side = tid & 1;
            float s = 0.f;
            #pragma unroll
            for (int h4 = 0; h4 < 16; ++h4) {
                float4 q4 = *(const float4*)&qt[r*QS + h4*4];
                s += q4.x * kt[(h4*4+0)*AS + CH + side];
                s += q4.y * kt[(h4*4+1)*AS + CH + side];
                s += q4.z * kt[(h4*4+2)*AS + CH + side];
                s += q4.w * kt[(h4*4+3)*AS + CH + side];
            }
            aLR[side*AR + r] = s * SCALE;
        }
        __syncthreads();

        // ---- conv3x3 + sigmoid + relu + expm1 -> e, rowsum ----
        {
            const float w0=cw[0],w1=cw[1],w2=cw[2],w3=cw[3],w4=cw[4],
                        w5=cw[5],w6=cw[6],w7=cw[7],w8=cw[8],cb=cw[9];
            #pragma unroll 1
            for (int it = 0; it < 16; ++it) {
                int idx = tid + it*512;
                bool act = idx < R_*CH;          // 7936; warp-uniform
                int r = (idx >> 7) + 1;          // 1..62
                int c = idx & 127;
                float ev = 0.f;
                if (act) {
                    const float* am = a + (r-1)*AS;
                    const float* ac = a + r*AS;
                    const float* ap = a + (r+1)*AS;
                    float l0 = (c>0)    ? am[c-1] : aLR[r-1];
                    float l1 = am[c];
                    float l2 = (c<CH-1) ? am[c+1] : aLR[AR + r-1];
                    float c0 = (c>0)    ? ac[c-1] : aLR[r];
                    float c1 = ac[c];
                    float c2 = (c<CH-1) ? ac[c+1] : aLR[AR + r];
                    float d0 = (c>0)    ? ap[c-1] : aLR[r+1];
                    float d1 = ap[c];
                    float d2 = (c<CH-1) ? ap[c+1] : aLR[AR + r+1];
                    float conv = cb + w0*l0 + w1*l1 + w2*l2
                                    + w3*c0 + w4*c1 + w5*c2
                                    + w6*d0 + w7*d1 + w8*d2;
                    float sig = __fdividef(1.f, 1.f + __expf(-conv));
                    float xx = fmaxf(c1 - sig, 0.f);
                    ev = __expf(xx) - 1.f;
                    e[r*AS + c] = ev;
                }
                float ps = ev;
                #pragma unroll
                for (int off = 16; off > 0; off >>= 1)
                    ps += __shfl_down_sync(0xffffffffu, ps, off);
                if (act && (tid & 31) == 0) atomicAdd(&rowsum[r], ps);
            }
        }
        __syncthreads();

        // ---- PV accumulate: group g handles m in [g*64, g*64+64) ----
        {
            const int mbase = g*64;
            #pragma unroll 4
            for (int ms = 0; ms < 16; ++ms) {
                int m0 = mbase + ms*4;
                float evv[4][4], vv[4][4];
                #pragma unroll
                for (int i = 0; i < 4; ++i) {
                    float4 t = *(const float4*)&e[(prg*4+i)*AS + m0];
                    evv[i][0]=t.x; evv[i][1]=t.y; evv[i][2]=t.z; evv[i][3]=t.w;
                }
                #pragma unroll
                for (int u = 0; u < 4; ++u) {
                    float4 t = *(const float4*)&vt[(m0+u)*H_ + phg*4];
                    vv[u][0]=t.x; vv[u][1]=t.y; vv[u][2]=t.z; vv[u][3]=t.w;
                }
                #pragma unroll
                for (int i = 0; i < 4; ++i)
                    #pragma unroll
                    for (int j = 0; j < 4; ++j)
                        pv[i][j] += evv[i][0]*vv[0][j] + evv[i][1]*vv[1][j]
                                  + evv[i][2]*vv[2][j] + evv[i][3]*vv[3][j];
            }
        }
        __syncthreads();   // protects kt/vt/a/e before next chunk
    }

    // ---- reduce the 2 m-halves (scratch reuses a and e), normalize, store ----
    {
        float* sc = g ? e : a;       // [64][64] each
        #pragma unroll
        for (int i = 0; i < 4; ++i) {
            float4 t;
            t.x = pv[i][0]; t.y = pv[i][1]; t.z = pv[i][2]; t.w = pv[i][3];
            *(float4*)&sc[(prg*4+i)*H_ + phg*4] = t;
        }
        __syncthreads();
        for (int idx = tid; idx < R_*16; idx += 512) {
            int r = (idx >> 4) + 1;          // e-row 1..62
            int h4 = idx & 15;
            float4 x4 = *(const float4*)&a[r*H_ + h4*4];
            float4 y4 = *(const float4*)&e[r*H_ + h4*4];
            int gr = r0 + (r - 1);
            if (gr < N_) {
                float inv = __fdividef(1.f, rowsum[r] + 1e-5f);
                float4 o;
                o.x = (x4.x + y4.x)*inv; o.y = (x4.y + y4.y)*inv;
                o.z = (x4.z + y4.z)*inv; o.w = (x4.w + y4.w)*inv;
                *(float4*)&out[((size_t)b*N_ + gr)*H_ + h4*4] = o;
            }
        }
    }
}

// ---------------------------------------------------------------------------
extern "C" void kernel_launch(void* const* d_in, const int* in_sizes, int n_in,
                              void* d_out, int out_size)
{
    const float* x  = (const float*)d_in[0];
    const float* Wq = (const float*)d_in[1];
    const float* bq = (const float*)d_in[2];
    const float* Wk = (const float*)d_in[3];
    const float* bk = (const float*)d_in[4];
    const float* Wv = (const float*)d_in[5];
    const float* bv = (const float*)d_in[6];
    const float* cw = (const float*)d_in[7];
    const float* cb = (const float*)d_in[8];
    float* out = (float*)d_out;

    qkv_kernel_75625784<<<dim3(512, 3), 256>>>(x, Wq, bq, Wk, bk, Wv, bv);

    const size_t smem_bytes =
        (size_t)(3*AR*AS + AR*QS + CH*H_ + 2*AR + AR + 16) * sizeof(float);
    cudaFuncSetAttribute(attn2_kernel_75625784,
                         cudaFuncAttributeMaxDynamicSharedMemorySize,
                         (int)smem_bytes);
    attn2_kernel_75625784<<<dim3(NT, B_), 512, smem_bytes>>>(cw, cb, out);
}

// round 12
// speedup vs baseline: 1.2975x; 1.2975x over previous
#include <cuda_runtime.h>
#include <cuda_bf16.h>
#include <cstdint>

#define B_ 16
#define N_ 2048
#define D_ 256
#define H_ 64
#define R_ 62            // output rows per tile
#define AR 64            // A rows incl. 2 halo rows
#define NT 34            // ceil(N_/R_)
#define CH 128           // m-chunk columns
#define NCH 16           // N_/CH
#define AS 132           // fp32 col stride for a
#define QSB 72           // bf16 row stride qhi/qlo
#define KTSB 136         // bf16 row stride kthi/ktlo
#define ESB 136          // bf16 row stride ehi/elo
#define VSB 72           // bf16 row stride vhi/vlo

// bf16 hi/lo planes produced by the QKV kernel
__device__ __nv_bfloat16 g_qhi[B_*N_*H_];   // [b][n][h], pre-scaled by H^-0.5
__device__ __nv_bfloat16 g_qlo[B_*N_*H_];
__device__ __nv_bfloat16 g_kthi[B_*H_*N_];  // [b][h][n]  (transposed)
__device__ __nv_bfloat16 g_ktlo[B_*H_*N_];
__device__ __nv_bfloat16 g_vhi[B_*N_*H_];   // [b][n][h]
__device__ __nv_bfloat16 g_vlo[B_*N_*H_];

// ---------------------------------------------------------------------------
// helpers
// ---------------------------------------------------------------------------
__device__ __forceinline__ uint32_t bfpack_hi(float x, float y) {
    __nv_bfloat162 t;
    t.x = __float2bfloat16(x);
    t.y = __float2bfloat16(y);
    return *reinterpret_cast<uint32_t*>(&t);
}
__device__ __forceinline__ uint32_t bfpack_lo(float x, float y) {
    float rx = x - __bfloat162float(__float2bfloat16(x));
    float ry = y - __bfloat162float(__float2bfloat16(y));
    return bfpack_hi(rx, ry);
}
__device__ __forceinline__ uint32_t smaddr(const void* p) {
    return (uint32_t)__cvta_generic_to_shared(p);
}
__device__ __forceinline__ void ldsm4(uint32_t a, uint32_t& r0, uint32_t& r1,
                                      uint32_t& r2, uint32_t& r3) {
    asm volatile("ldmatrix.sync.aligned.m8n8.x4.shared.b16 {%0,%1,%2,%3},[%4];"
                 : "=r"(r0), "=r"(r1), "=r"(r2), "=r"(r3) : "r"(a));
}
__device__ __forceinline__ void ldsm4t(uint32_t a, uint32_t& r0, uint32_t& r1,
                                       uint32_t& r2, uint32_t& r3) {
    asm volatile("ldmatrix.sync.aligned.m8n8.x4.trans.shared.b16 {%0,%1,%2,%3},[%4];"
                 : "=r"(r0), "=r"(r1), "=r"(r2), "=r"(r3) : "r"(a));
}
__device__ __forceinline__ void mma16816(float* c, const uint32_t* a,
                                         uint32_t b0, uint32_t b1) {
    asm volatile(
        "mma.sync.aligned.m16n8k16.row.col.f32.bf16.bf16.f32 "
        "{%0,%1,%2,%3},{%4,%5,%6,%7},{%8,%9},{%0,%1,%2,%3};"
        : "+f"(c[0]), "+f"(c[1]), "+f"(c[2]), "+f"(c[3])
        : "r"(a[0]), "r"(a[1]), "r"(a[2]), "r"(a[3]), "r"(b0), "r"(b1));
}

// ---------------------------------------------------------------------------
// Kernel 1: QKV projection -> bf16 hi/lo planes (k transposed, q pre-scaled)
// grid = (512, 3), 256 threads
// ---------------------------------------------------------------------------
__global__ __launch_bounds__(256) void qkv_kernel_75625784(
    const float* __restrict__ x,
    const float* __restrict__ Wq, const float* __restrict__ bq,
    const float* __restrict__ Wk, const float* __restrict__ bk,
    const float* __restrict__ Wv, const float* __restrict__ bv)
{
    __shared__ float xs[64*64];
    __shared__ float ws[64*64];
    const int mat = blockIdx.y;
    const float* W    = (mat==0) ? Wq : (mat==1 ? Wk : Wv);
    const float* bias = (mat==0) ? bq : (mat==1 ? bk : bv);
    const int row0 = blockIdx.x * 64;
    const int tid = threadIdx.x;
    const int rt = tid >> 4;
    const int ht = tid & 15;

    float acc[4][4];
    #pragma unroll
    for (int i = 0; i < 4; ++i)
        #pragma unroll
        for (int j = 0; j < 4; ++j) acc[i][j] = 0.f;

    for (int dc = 0; dc < D_; dc += 64) {
        #pragma unroll
        for (int it = 0; it < 4; ++it) {
            int fi = it*256 + tid;
            int r = fi >> 4, c4 = fi & 15;
            *(float4*)&xs[r*64 + c4*4] =
                *(const float4*)&x[(size_t)(row0 + r)*D_ + dc + c4*4];
            *(float4*)&ws[r*64 + c4*4] =
                *(const float4*)&W[(size_t)(dc + r)*H_ + c4*4];
        }
        __syncthreads();
        #pragma unroll
        for (int d4 = 0; d4 < 16; ++d4) {
            float av[4][4], bv4[4][4];
            #pragma unroll
            for (int i = 0; i < 4; ++i) {
                float4 t = *(const float4*)&xs[(rt*4+i)*64 + d4*4];
                av[i][0]=t.x; av[i][1]=t.y; av[i][2]=t.z; av[i][3]=t.w;
            }
            #pragma unroll
            for (int u = 0; u < 4; ++u) {
                float4 t = *(const float4*)&ws[(d4*4+u)*64 + ht*4];
                bv4[u][0]=t.x; bv4[u][1]=t.y; bv4[u][2]=t.z; bv4[u][3]=t.w;
            }
            #pragma unroll
            for (int i = 0; i < 4; ++i)
                #pragma unroll
                for (int j = 0; j < 4; ++j)
                    acc[i][j] += av[i][0]*bv4[0][j] + av[i][1]*bv4[1][j]
                               + av[i][2]*bv4[2][j] + av[i][3]*bv4[3][j];
        }
        __syncthreads();
    }
    float4 bb = *(const float4*)&bias[ht*4];

    if (mat != 1) {
        const float sc = (mat == 0) ? 0.125f : 1.f;
        uint32_t* ghi = (uint32_t*)(mat==0 ? (void*)g_qhi : (void*)g_vhi);
        uint32_t* glo = (uint32_t*)(mat==0 ? (void*)g_qlo : (void*)g_vlo);
        #pragma unroll
        for (int i = 0; i < 4; ++i) {
            int row = row0 + rt*4 + i;
            float v0 = (acc[i][0]+bb.x)*sc, v1 = (acc[i][1]+bb.y)*sc;
            float v2 = (acc[i][2]+bb.z)*sc, v3 = (acc[i][3]+bb.w)*sc;
            size_t p = (size_t)row*32 + ht*2;         // uint32 index (2 bf16 each)
            ghi[p]   = bfpack_hi(v0, v1); ghi[p+1] = bfpack_hi(v2, v3);
            glo[p]   = bfpack_lo(v0, v1); glo[p+1] = bfpack_lo(v2, v3);
        }
    } else {
        // write tile transposed into xs[h][n_local], then store coalesced by h
        float bj[4] = {bb.x, bb.y, bb.z, bb.w};
        #pragma unroll
        for (int i = 0; i < 4; ++i)
            #pragma unroll
            for (int j = 0; j < 4; ++j)
                xs[(ht*4+j)*64 + rt*4 + i] = acc[i][j] + bj[j];
        __syncthreads();
        int h = tid >> 2, m0l = (tid & 3) * 16;
        int bI = row0 >> 11, n0 = row0 & 2047;
        uint32_t* ghi = (uint32_t*)g_kthi;
        uint32_t* glo = (uint32_t*)g_ktlo;
        size_t p = (((size_t)(bI*H_ + h))*N_ + n0 + m0l) >> 1;
        #pragma unroll
        for (int mm = 0; mm < 8; ++mm) {
            float x0 = xs[h*64 + m0l + 2*mm];
            float x1 = xs[h*64 + m0l + 2*mm + 1];
            ghi[p+mm] = bfpack_hi(x0, x1);
            glo[p+mm] = bfpack_lo(x0, x1);
        }
    }
}

// ---------------------------------------------------------------------------
// Kernel 2: fused attention, tensor-core QK / PV (bf16 split mma), SIMT conv
// grid = (NT, B_), 512 threads, ~156 KB smem
// ---------------------------------------------------------------------------
__global__ __launch_bounds__(512, 1) void attn3_kernel_75625784(
    const float* __restrict__ conv_w, const float* __restrict__ conv_b,
    float* __restrict__ out)
{
    extern __shared__ __align__(16) float sm[];
    float* a = sm;                                             // [64][AS] fp32
    __nv_bfloat16* qhi  = (__nv_bfloat16*)(sm + AR*AS);        // [64][QSB]
    __nv_bfloat16* qlo  = qhi  + AR*QSB;
    __nv_bfloat16* kthi = qlo  + AR*QSB;                       // [64][KTSB]
    __nv_bfloat16* ktlo = kthi + H_*KTSB;
    __nv_bfloat16* ehi  = ktlo + H_*KTSB;                      // [64][ESB]
    __nv_bfloat16* elo  = ehi  + AR*ESB;
    __nv_bfloat16* vhi  = elo  + AR*ESB;                       // [128][VSB]
    __nv_bfloat16* vlo  = vhi  + CH*VSB;
    float* kh     = (float*)(vlo + CH*VSB);                    // [2][64] halo k fp32
    float* aLR    = kh + 128;                                  // [2][64]
    float* rowsum = aLR + 128;                                 // [64]
    float* cw     = rowsum + 64;                               // [10]

    const int b   = blockIdx.y;
    const int r0  = blockIdx.x * R_;
    const int tid = threadIdx.x;
    const int lane = tid & 31;
    const int w    = tid >> 5;

    if (tid < AR) rowsum[tid] = 0.f;
    if (tid >= 64 && tid < 73) cw[tid-64] = conv_w[tid-64];
    if (tid == 73) cw[9] = conv_b[0];

    // q tile hi/lo (rows 0..63 = gr r0-1 .. r0+62; OOB rows zero)
    {
        int r = tid >> 3, j = tid & 7;
        int gr = r0 - 1 + r;
        uint4 zz = make_uint4(0u,0u,0u,0u);
        uint4 vh = zz, vl = zz;
        if (gr >= 0 && gr < N_) {
            size_t g = ((size_t)(b*N_ + gr))*H_ + j*8;
            vh = *(const uint4*)&g_qhi[g];
            vl = *(const uint4*)&g_qlo[g];
        }
        *(uint4*)&qhi[r*QSB + j*8] = vh;
        *(uint4*)&qlo[r*QSB + j*8] = vl;
    }
    // e halo rows 0 and 63 permanently zero
    if (tid < 256) {
        int r = (tid >> 7) ? 63 : 0;
        int c = tid & 127;
        ehi[r*ESB + c] = __float2bfloat16(0.f);
        elo[r*ESB + c] = __float2bfloat16(0.f);
    }
    __syncthreads();

    // warp tiles
    const int rb = (w >> 2) * 16;       // row base (a-row space)
    const int cb2 = (w & 3) * 32;       // QK col base
    const int hb = (w & 3) * 16;        // PV h base
    const int lr = lane & 15;
    const int lc = (lane >> 4) << 3;
    const int cr = lane >> 2;
    const int cc = (lane & 3) * 2;

    const uint32_t qhiU  = smaddr(qhi),  qloU  = smaddr(qlo);
    const uint32_t kthiU = smaddr(kthi), ktloU = smaddr(ktlo);
    const uint32_t ehiU  = smaddr(ehi),  eloU  = smaddr(elo);
    const uint32_t vhiU  = smaddr(vhi),  vloU  = smaddr(vlo);

    float pv[2][4];
    #pragma unroll
    for (int n = 0; n < 2; ++n)
        #pragma unroll
        for (int i = 0; i < 4; ++i) pv[n][i] = 0.f;

    for (int ch = 0; ch < NCH; ++ch) {
        const int mb = ch * CH;

        // ---- loads: kt chunk, v chunk (uint4 coalesced), halo k fp32 ----
        #pragma unroll
        for (int it = 0; it < 2; ++it) {
            int f = tid + it*512;                // 0..1023
            int h = f >> 4, j = f & 15;
            size_t g = ((size_t)(b*H_ + h))*N_ + mb + j*8;
            *(uint4*)&kthi[h*KTSB + j*8] = *(const uint4*)&g_kthi[g];
            *(uint4*)&ktlo[h*KTSB + j*8] = *(const uint4*)&g_ktlo[g];
        }
        #pragma unroll
        for (int it = 0; it < 2; ++it) {
            int f = tid + it*512;
            int m = f >> 3, j = f & 7;
            size_t g = ((size_t)(b*N_ + mb + m))*H_ + j*8;
            *(uint4*)&vhi[m*VSB + j*8] = *(const uint4*)&g_vhi[g];
            *(uint4*)&vlo[m*VSB + j*8] = *(const uint4*)&g_vlo[g];
        }
        if (tid < 128) {
            int side = tid >> 6, hh = tid & 63;
            int m = side ? (mb + CH) : (mb - 1);
            float v = 0.f;
            if (m >= 0 && m < N_) {
                size_t g = ((size_t)(b*H_ + hh))*N_ + m;
                v = __bfloat162float(g_kthi[g]) + __bfloat162float(g_ktlo[g]);
            }
            kh[side*64 + hh] = v;
        }
        __syncthreads();

        // ---- QK via mma: a[64][128] = q @ kt (q pre-scaled) ----
        {
            float cacc[4][4];
            #pragma unroll
            for (int n = 0; n < 4; ++n)
                #pragma unroll
                for (int i = 0; i < 4; ++i) cacc[n][i] = 0.f;
            #pragma unroll
            for (int kk = 0; kk < 4; ++kk) {
                const int k0 = kk*16;
                uint32_t ah[4], al[4];
                ldsm4(qhiU + ((rb+lr)*QSB + k0 + lc)*2, ah[0],ah[1],ah[2],ah[3]);
                ldsm4(qloU + ((rb+lr)*QSB + k0 + lc)*2, al[0],al[1],al[2],al[3]);
                #pragma unroll
                for (int nb = 0; nb < 2; ++nb) {
                    const int n0 = cb2 + nb*16;
                    uint32_t bh[4], bl[4];
                    ldsm4t(kthiU + ((k0+lr)*KTSB + n0 + lc)*2, bh[0],bh[1],bh[2],bh[3]);
                    ldsm4t(ktloU + ((k0+lr)*KTSB + n0 + lc)*2, bl[0],bl[1],bl[2],bl[3]);
                    mma16816(cacc[nb*2+0], ah, bh[0], bh[1]);
                    mma16816(cacc[nb*2+0], ah, bl[0], bl[1]);
                    mma16816(cacc[nb*2+0], al, bh[0], bh[1]);
                    mma16816(cacc[nb*2+1], ah, bh[2], bh[3]);
                    mma16816(cacc[nb*2+1], ah, bl[2], bl[3]);
                    mma16816(cacc[nb*2+1], al, bh[2], bh[3]);
                }
            }
            #pragma unroll
            for (int nt = 0; nt < 4; ++nt) {
                int col = cb2 + nt*8 + cc;
                *(float2*)&a[(rb+cr  )*AS + col] = make_float2(cacc[nt][0], cacc[nt][1]);
                *(float2*)&a[(rb+cr+8)*AS + col] = make_float2(cacc[nt][2], cacc[nt][3]);
            }
        }
        // ---- QK halo columns (SIMT fp32) ----
        if (tid < 128) {
            int r = tid >> 1, side = tid & 1;
            float s = 0.f;
            #pragma unroll 16
            for (int h = 0; h < H_; ++h) {
                float qf = __bfloat162float(qhi[r*QSB + h])
                         + __bfloat162float(qlo[r*QSB + h]);
                s += qf * kh[side*64 + h];
            }
            aLR[side*64 + r] = s;
        }
        __syncthreads();

        // ---- conv3x3 + sigmoid + relu + expm1 -> ehi/elo, rowsum ----
        {
            const float w0=cw[0],w1=cw[1],w2=cw[2],w3=cw[3],w4=cw[4],
                        w5=cw[5],w6=cw[6],w7=cw[7],w8=cw[8],cb=cw[9];
            #pragma unroll 1
            for (int it = 0; it < 16; ++it) {
                int idx = tid + it*512;
                bool act = idx < R_*CH;
                int r = (idx >> 7) + 1;
                int c = idx & 127;
                float ev = 0.f;
                if (act) {
                    const float* am = a + (r-1)*AS;
                    const float* ac = a + r*AS;
                    const float* ap = a + (r+1)*AS;
                    float l0 = (c>0)    ? am[c-1] : aLR[r-1];
                    float l1 = am[c];
                    float l2 = (c<CH-1) ? am[c+1] : aLR[64 + r-1];
                    float c0 = (c>0)    ? ac[c-1] : aLR[r];
                    float c1 = ac[c];
                    float c2 = (c<CH-1) ? ac[c+1] : aLR[64 + r];
                    float d0 = (c>0)    ? ap[c-1] : aLR[r+1];
                    float d1 = ap[c];
                    float d2 = (c<CH-1) ? ap[c+1] : aLR[64 + r+1];
                    float conv = cb + w0*l0 + w1*l1 + w2*l2
                                    + w3*c0 + w4*c1 + w5*c2
                                    + w6*d0 + w7*d1 + w8*d2;
                    float sig = __fdividef(1.f, 1.f + __expf(-conv));
                    float xx = fmaxf(c1 - sig, 0.f);
                    ev = __expf(xx) - 1.f;
                    __nv_bfloat16 h16 = __float2bfloat16(ev);
                    ehi[r*ESB + c] = h16;
                    elo[r*ESB + c] = __float2bfloat16(ev - __bfloat162float(h16));
                }
                float ps = ev;
                #pragma unroll
                for (int off = 16; off > 0; off >>= 1)
                    ps += __shfl_down_sync(0xffffffffu, ps, off);
                if (act && lane == 0) atomicAdd(&rowsum[r], ps);
            }
        }
        __syncthreads();

        // ---- PV via mma: pv += e[64][128] @ v[128][64], per-warp 16x16 tile ----
        #pragma unroll
        for (int kk = 0; kk < 8; ++kk) {
            const int k0 = kk*16;
            uint32_t ah[4], al[4];
            ldsm4(ehiU + ((rb+lr)*ESB + k0 + lc)*2, ah[0],ah[1],ah[2],ah[3]);
            ldsm4(eloU + ((rb+lr)*ESB + k0 + lc)*2, al[0],al[1],al[2],al[3]);
            uint32_t bh[4], bl[4];
            ldsm4t(vhiU + ((k0+lr)*VSB + hb + lc)*2, bh[0],bh[1],bh[2],bh[3]);
            ldsm4t(vloU + ((k0+lr)*VSB + hb + lc)*2, bl[0],bl[1],bl[2],bl[3]);
            mma16816(pv[0], ah, bh[0], bh[1]);
            mma16816(pv[0], ah, bl[0], bl[1]);
            mma16816(pv[0], al, bh[0], bh[1]);
            mma16816(pv[1], ah, bh[2], bh[3]);
            mma16816(pv[1], ah, bl[2], bl[3]);
            mma16816(pv[1], al, bh[2], bh[3]);
        }
        __syncthreads();   // protect kt/v/a/e before next chunk
    }

    // ---- normalize + store (per-warp tile, no reduction needed) ----
    {
        #pragma unroll
        for (int half = 0; half < 2; ++half) {
            int ar = rb + cr + half*8;
            if (ar >= 1 && ar <= R_) {
                int gr = r0 + ar - 1;
                if (gr < N_) {
                    float inv = __fdividef(1.f, rowsum[ar] + 1e-5f);
                    #pragma unroll
                    for (int nb = 0; nb < 2; ++nb) {
                        int col = hb + nb*8 + cc;
                        float2 o = make_float2(pv[nb][half*2+0]*inv,
                                               pv[nb][half*2+1]*inv);
                        *(float2*)&out[((size_t)(b*N_ + gr))*H_ + col] = o;
                    }
                }
            }
        }
    }
}

// ---------------------------------------------------------------------------
extern "C" void kernel_launch(void* const* d_in, const int* in_sizes, int n_in,
                              void* d_out, int out_size)
{
    const float* x  = (const float*)d_in[0];
    const float* Wq = (const float*)d_in[1];
    const float* bq = (const float*)d_in[2];
    const float* Wk = (const float*)d_in[3];
    const float* bk = (const float*)d_in[4];
    const float* Wv = (const float*)d_in[5];
    const float* bv = (const float*)d_in[6];
    const float* cw = (const float*)d_in[7];
    const float* cb = (const float*)d_in[8];
    float* out = (float*)d_out;

    qkv_kernel_75625784<<<dim3(512, 3), 256>>>(x, Wq, bq, Wk, bk, Wv, bv);

    const size_t smem_bytes =
        (size_t)AR*AS*4                    // a
        + (size_t)2*AR*QSB*2               // qhi/qlo
        + (size_t)2*H_*KTSB*2              // kthi/ktlo
        + (size_t)2*AR*ESB*2               // ehi/elo
        + (size_t)2*CH*VSB*2               // vhi/vlo
        + (128 + 128 + 64 + 16)*4;         // kh, aLR, rowsum, cw
    cudaFuncSetAttribute(attn3_kernel_75625784,
                         cudaFuncAttributeMaxDynamicSharedMemorySize,
                         (int)smem_bytes);
    attn3_kernel_75625784<<<dim3(NT, B_), 512, smem_bytes>>>(cw, cb, out);
}

// round 17
// speedup vs baseline: 1.9485x; 1.5017x over previous
#include <cuda_runtime.h>
#include <cuda_bf16.h>
#include <cstdint>

#define B_ 16
#define N_ 2048
#define D_ 256
#define H_ 64
#define R_ 62            // output rows per tile
#define AR 64            // A rows incl. 2 halo rows
#define NT 34            // ceil(N_/R_)
#define CH 128           // m-chunk columns
#define NCH 16           // N_/CH
#define AS 132           // fp32 col stride for a
#define QSB 72           // bf16 row stride qhi/qlo
#define KTSB 136         // bf16 row stride kthi/ktlo
#define ESB 136          // bf16 row stride ehi/elo
#define VSB 72           // bf16 row stride vhi/vlo

#define KT_PLANE (H_*KTSB)       // 8704 bf16
#define KT_BUF   (2*KT_PLANE)    // 17408 bf16 per buffer (hi+lo)
#define V_PLANE  (CH*VSB)        // 9216 bf16
#define V_BUF    (2*V_PLANE)     // 18432 bf16 per buffer
#define AE_FLOATS 8704           // max(a fp32 region, e bf16 planes) = 34816 B

// bf16 hi/lo planes produced by the QKV kernel
__device__ __nv_bfloat16 g_qhi[B_*N_*H_];   // [b][n][h], pre-scaled by H^-0.5
__device__ __nv_bfloat16 g_qlo[B_*N_*H_];
__device__ __nv_bfloat16 g_kthi[B_*H_*N_];  // [b][h][n]  (transposed)
__device__ __nv_bfloat16 g_ktlo[B_*H_*N_];
__device__ __nv_bfloat16 g_vhi[B_*N_*H_];   // [b][n][h]
__device__ __nv_bfloat16 g_vlo[B_*N_*H_];

// ---------------------------------------------------------------------------
// helpers
// ---------------------------------------------------------------------------
__device__ __forceinline__ uint32_t bfpack_hi(float x, float y) {
    __nv_bfloat162 t;
    t.x = __float2bfloat16(x);
    t.y = __float2bfloat16(y);
    return *reinterpret_cast<uint32_t*>(&t);
}
__device__ __forceinline__ uint32_t bfpack_lo(float x, float y) {
    float rx = x - __bfloat162float(__float2bfloat16(x));
    float ry = y - __bfloat162float(__float2bfloat16(y));
    return bfpack_hi(rx, ry);
}
__device__ __forceinline__ uint32_t smaddr(const void* p) {
    return (uint32_t)__cvta_generic_to_shared(p);
}
__device__ __forceinline__ void ldsm4(uint32_t a, uint32_t& r0, uint32_t& r1,
                                      uint32_t& r2, uint32_t& r3) {
    asm volatile("ldmatrix.sync.aligned.m8n8.x4.shared.b16 {%0,%1,%2,%3},[%4];"
                 : "=r"(r0), "=r"(r1), "=r"(r2), "=r"(r3) : "r"(a));
}
__device__ __forceinline__ void ldsm4t(uint32_t a, uint32_t& r0, uint32_t& r1,
                                       uint32_t& r2, uint32_t& r3) {
    asm volatile("ldmatrix.sync.aligned.m8n8.x4.trans.shared.b16 {%0,%1,%2,%3},[%4];"
                 : "=r"(r0), "=r"(r1), "=r"(r2), "=r"(r3) : "r"(a));
}
__device__ __forceinline__ void mma16816(float* c, const uint32_t* a,
                                         uint32_t b0, uint32_t b1) {
    asm volatile(
        "mma.sync.aligned.m16n8k16.row.col.f32.bf16.bf16.f32 "
        "{%0,%1,%2,%3},{%4,%5,%6,%7},{%8,%9},{%0,%1,%2,%3};"
        : "+f"(c[0]), "+f"(c[1]), "+f"(c[2]), "+f"(c[3])
        : "r"(a[0]), "r"(a[1]), "r"(a[2]), "r"(a[3]), "r"(b0), "r"(b1));
}
__device__ __forceinline__ void cp16(uint32_t dst, const void* src) {
    asm volatile("cp.async.cg.shared.global [%0], [%1], 16;" :: "r"(dst), "l"(src));
}
__device__ __forceinline__ void cp_commit() {
    asm volatile("cp.async.commit_group;");
}
__device__ __forceinline__ void cp_wait0() {
    asm volatile("cp.async.wait_group 0;");
}

// ---------------------------------------------------------------------------
// Kernel 1: QKV projection -> bf16 hi/lo planes (k transposed, q pre-scaled)
// grid = (512, 3), 256 threads
// ---------------------------------------------------------------------------
__global__ __launch_bounds__(256) void qkv_kernel_75625784(
    const float* __restrict__ x,
    const float* __restrict__ Wq, const float* __restrict__ bq,
    const float* __restrict__ Wk, const float* __restrict__ bk,
    const float* __restrict__ Wv, const float* __restrict__ bv)
{
    __shared__ float xs[64*64];
    __shared__ float ws[64*64];
    const int mat = blockIdx.y;
    const float* W    = (mat==0) ? Wq : (mat==1 ? Wk : Wv);
    const float* bias = (mat==0) ? bq : (mat==1 ? bk : bv);
    const int row0 = blockIdx.x * 64;
    const int tid = threadIdx.x;
    const int rt = tid >> 4;
    const int ht = tid & 15;

    float acc[4][4];
    #pragma unroll
    for (int i = 0; i < 4; ++i)
        #pragma unroll
        for (int j = 0; j < 4; ++j) acc[i][j] = 0.f;

    for (int dc = 0; dc < D_; dc += 64) {
        #pragma unroll
        for (int it = 0; it < 4; ++it) {
            int fi = it*256 + tid;
            int r = fi >> 4, c4 = fi & 15;
            *(float4*)&xs[r*64 + c4*4] =
                *(const float4*)&x[(size_t)(row0 + r)*D_ + dc + c4*4];
            *(float4*)&ws[r*64 + c4*4] =
                *(const float4*)&W[(size_t)(dc + r)*H_ + c4*4];
        }
        __syncthreads();
        #pragma unroll
        for (int d4 = 0; d4 < 16; ++d4) {
            float av[4][4], bv4[4][4];
            #pragma unroll
            for (int i = 0; i < 4; ++i) {
                float4 t = *(const float4*)&xs[(rt*4+i)*64 + d4*4];
                av[i][0]=t.x; av[i][1]=t.y; av[i][2]=t.z; av[i][3]=t.w;
            }
            #pragma unroll
            for (int u = 0; u < 4; ++u) {
                float4 t = *(const float4*)&ws[(d4*4+u)*64 + ht*4];
                bv4[u][0]=t.x; bv4[u][1]=t.y; bv4[u][2]=t.z; bv4[u][3]=t.w;
            }
            #pragma unroll
            for (int i = 0; i < 4; ++i)
                #pragma unroll
                for (int j = 0; j < 4; ++j)
                    acc[i][j] += av[i][0]*bv4[0][j] + av[i][1]*bv4[1][j]
                               + av[i][2]*bv4[2][j] + av[i][3]*bv4[3][j];
        }
        __syncthreads();
    }
    float4 bb = *(const float4*)&bias[ht*4];

    if (mat != 1) {
        const float sc = (mat == 0) ? 0.125f : 1.f;
        uint32_t* ghi = (uint32_t*)(mat==0 ? (void*)g_qhi : (void*)g_vhi);
        uint32_t* glo = (uint32_t*)(mat==0 ? (void*)g_qlo : (void*)g_vlo);
        #pragma unroll
        for (int i = 0; i < 4; ++i) {
            int row = row0 + rt*4 + i;
            float v0 = (acc[i][0]+bb.x)*sc, v1 = (acc[i][1]+bb.y)*sc;
            float v2 = (acc[i][2]+bb.z)*sc, v3 = (acc[i][3]+bb.w)*sc;
            size_t p = (size_t)row*32 + ht*2;         // uint32 index (2 bf16 each)
            ghi[p]   = bfpack_hi(v0, v1); ghi[p+1] = bfpack_hi(v2, v3);
            glo[p]   = bfpack_lo(v0, v1); glo[p+1] = bfpack_lo(v2, v3);
        }
    } else {
        // write tile transposed into xs[h][n_local], then store coalesced by h
        float bj[4] = {bb.x, bb.y, bb.z, bb.w};
        #pragma unroll
        for (int i = 0; i < 4; ++i)
            #pragma unroll
            for (int j = 0; j < 4; ++j)
                xs[(ht*4+j)*64 + rt*4 + i] = acc[i][j] + bj[j];
        __syncthreads();
        int h = tid >> 2, m0l = (tid & 3) * 16;
        int bI = row0 >> 11, n0 = row0 & 2047;
        uint32_t* ghi = (uint32_t*)g_kthi;
        uint32_t* glo = (uint32_t*)g_ktlo;
        size_t p = (((size_t)(bI*H_ + h))*N_ + n0 + m0l) >> 1;
        #pragma unroll
        for (int mm = 0; mm < 8; ++mm) {
            float x0 = xs[h*64 + m0l + 2*mm];
            float x1 = xs[h*64 + m0l + 2*mm + 1];
            ghi[p+mm] = bfpack_hi(x0, x1);
            glo[p+mm] = bfpack_lo(x0, x1);
        }
    }
}

// ---------------------------------------------------------------------------
// Kernel 2: fused attention; tensor-core QK/PV, cp.async double-buffered
// chunk loads, a/e buffer aliasing, vectorized conv.
// grid = (NT, B_), 512 threads, ~193 KB smem
// ---------------------------------------------------------------------------
__global__ __launch_bounds__(512, 1) void attn4_kernel_75625784(
    const float* __restrict__ conv_w, const float* __restrict__ conv_b,
    float* __restrict__ out)
{
    extern __shared__ __align__(16) float sm[];
    float* aa = sm;                                   // [64][AS] fp32  (aliased)
    __nv_bfloat16* ehi = (__nv_bfloat16*)sm;          // [64][ESB]      (aliased)
    __nv_bfloat16* elo = ehi + AR*ESB;
    __nv_bfloat16* qhi = (__nv_bfloat16*)(sm + AE_FLOATS);  // [64][QSB]
    __nv_bfloat16* qlo = qhi + AR*QSB;
    __nv_bfloat16* kt0 = qlo + AR*QSB;                // 2 x KT_BUF
    __nv_bfloat16* v0  = kt0 + 2*KT_BUF;              // 2 x V_BUF
    float* aLR    = (float*)(v0 + 2*V_BUF);           // [2][64]
    float* rowsum = aLR + 2*AR;                       // [64]
    float* cw     = rowsum + AR;                      // [10]

    const int b   = blockIdx.y;
    const int r0  = blockIdx.x * R_;
    const int tid = threadIdx.x;
    const int lane = tid & 31;
    const int w    = tid >> 5;

    const uint32_t ktU = smaddr(kt0);
    const uint32_t vU  = smaddr(v0);
    const uint32_t aeU = smaddr(sm);
    const uint32_t qhiU = smaddr(qhi), qloU = smaddr(qlo);

    // ---- prefetch chunk 0 immediately ----
    {
        const int mc = 0;
        #pragma unroll
        for (int it = 0; it < 2; ++it) {
            int f = tid + it*512;
            int h = f >> 4, j = (f & 15)*8;
            size_t g = ((size_t)(b*H_ + h))*N_ + mc + j;
            cp16(ktU + (h*KTSB + j)*2, g_kthi + g);
            cp16(ktU + (KT_PLANE + h*KTSB + j)*2, g_ktlo + g);
        }
        #pragma unroll
        for (int it = 0; it < 2; ++it) {
            int f = tid + it*512;
            int m = f >> 3, j = (f & 7)*8;
            size_t g = ((size_t)(b*N_ + mc + m))*H_ + j;
            cp16(vU + (m*VSB + j)*2, g_vhi + g);
            cp16(vU + (V_PLANE + m*VSB + j)*2, g_vlo + g);
        }
        cp_commit();
    }

    if (tid < AR) rowsum[tid] = 0.f;
    if (tid >= 64 && tid < 73) cw[tid-64] = conv_w[tid-64];
    if (tid == 73) cw[9] = conv_b[0];

    // q tile hi/lo (rows 0..63 = gr r0-1 .. r0+62; OOB rows zero)
    {
        int r = tid >> 3, j = tid & 7;
        int gr = r0 - 1 + r;
        uint4 zz = make_uint4(0u,0u,0u,0u);
        uint4 vh = zz, vl = zz;
        if (gr >= 0 && gr < N_) {
            size_t g = ((size_t)(b*N_ + gr))*H_ + j*8;
            vh = *(const uint4*)&g_qhi[g];
            vl = *(const uint4*)&g_qlo[g];
        }
        *(uint4*)&qhi[r*QSB + j*8] = vh;
        *(uint4*)&qlo[r*QSB + j*8] = vl;
    }
    __syncthreads();

    // warp tiles
    const int rb  = (w >> 2) * 16;      // row base (a-row space)
    const int cb2 = (w & 3) * 32;       // QK col base
    const int hb  = (w & 3) * 16;       // PV h base
    const int lr = lane & 15;
    const int lc = (lane >> 4) << 3;
    const int cr = lane >> 2;
    const int cc = (lane & 3) * 2;

    // ---- preload q fragments once (invariant across chunks) ----
    uint32_t qa[4][4], qb[4][4];
    #pragma unroll
    for (int kk = 0; kk < 4; ++kk) {
        ldsm4(qhiU + ((rb+lr)*QSB + kk*16 + lc)*2, qa[kk][0],qa[kk][1],qa[kk][2],qa[kk][3]);
        ldsm4(qloU + ((rb+lr)*QSB + kk*16 + lc)*2, qb[kk][0],qb[kk][1],qb[kk][2],qb[kk][3]);
    }

    float pv[2][4];
    #pragma unroll
    for (int n = 0; n < 2; ++n)
        #pragma unroll
        for (int i = 0; i < 4; ++i) pv[n][i] = 0.f;

    int p = 0;
    for (int ch = 0; ch < NCH; ++ch) {
        const int mb = ch * CH;

        cp_wait0();
        __syncthreads();   // kt/v[p] ready; prev chunk's e reads done

        // ---- prefetch next chunk into the other buffer ----
        if (ch + 1 < NCH) {
            const int mc = mb + CH;
            const uint32_t ktb = ktU + (p^1)*KT_BUF*2;
            const uint32_t vb2 = vU  + (p^1)*V_BUF*2;
            #pragma unroll
            for (int it = 0; it < 2; ++it) {
                int f = tid + it*512;
                int h = f >> 4, j = (f & 15)*8;
                size_t g = ((size_t)(b*H_ + h))*N_ + mc + j;
                cp16(ktb + (h*KTSB + j)*2, g_kthi + g);
                cp16(ktb + (KT_PLANE + h*KTSB + j)*2, g_ktlo + g);
            }
            #pragma unroll
            for (int it = 0; it < 2; ++it) {
                int f = tid + it*512;
                int m = f >> 3, j = (f & 7)*8;
                size_t g = ((size_t)(b*N_ + mc + m))*H_ + j;
                cp16(vb2 + (m*VSB + j)*2, g_vhi + g);
                cp16(vb2 + (V_PLANE + m*VSB + j)*2, g_vlo + g);
            }
            cp_commit();
        }

        // ---- QK via mma: a[64][128] = q @ kt ----
        {
            const uint32_t ktb = ktU + p*KT_BUF*2;
            float cacc[4][4];
            #pragma unroll
            for (int n = 0; n < 4; ++n)
                #pragma unroll
                for (int i = 0; i < 4; ++i) cacc[n][i] = 0.f;
            #pragma unroll
            for (int kk = 0; kk < 4; ++kk) {
                const int k0 = kk*16;
                #pragma unroll
                for (int nb = 0; nb < 2; ++nb) {
                    const int n0 = cb2 + nb*16;
                    uint32_t bh[4], bl[4];
                    ldsm4t(ktb + ((k0+lr)*KTSB + n0 + lc)*2, bh[0],bh[1],bh[2],bh[3]);
                    ldsm4t(ktb + (KT_PLANE*2) + ((k0+lr)*KTSB + n0 + lc)*2,
                           bl[0],bl[1],bl[2],bl[3]);
                    mma16816(cacc[nb*2+0], qa[kk], bh[0], bh[1]);
                    mma16816(cacc[nb*2+0], qa[kk], bl[0], bl[1]);
                    mma16816(cacc[nb*2+0], qb[kk], bh[0], bh[1]);
                    mma16816(cacc[nb*2+1], qa[kk], bh[2], bh[3]);
                    mma16816(cacc[nb*2+1], qa[kk], bl[2], bl[3]);
                    mma16816(cacc[nb*2+1], qb[kk], bh[2], bh[3]);
                }
            }
            #pragma unroll
            for (int nt = 0; nt < 4; ++nt) {
                int col = cb2 + nt*8 + cc;
                *(float2*)&aa[(rb+cr  )*AS + col] = make_float2(cacc[nt][0], cacc[nt][1]);
                *(float2*)&aa[(rb+cr+8)*AS + col] = make_float2(cacc[nt][2], cacc[nt][3]);
            }
        }
        // ---- QK halo columns: direct-gmem dot (L2-resident, broadcast) ----
        if (tid < 128) {
            int r = tid >> 1, side = tid & 1;
            int m = side ? (mb + CH) : (mb - 1);
            float s = 0.f;
            if (m >= 0 && m < N_) {
                const __nv_bfloat16* khi = g_kthi + ((size_t)(b*H_))*N_ + m;
                const __nv_bfloat16* klo = g_ktlo + ((size_t)(b*H_))*N_ + m;
                #pragma unroll 16
                for (int h = 0; h < H_; ++h) {
                    float kf = __bfloat162float(khi[(size_t)h*N_])
                             + __bfloat162float(klo[(size_t)h*N_]);
                    float qf = __bfloat162float(qhi[r*QSB + h])
                             + __bfloat162float(qlo[r*QSB + h]);
                    s += qf * kf;
                }
            }
            aLR[side*64 + r] = s;
        }
        __syncthreads();   // a, aLR complete

        // ---- conv3x3 + sigmoid + relu + expm1 -> registers; rowsum ----
        float ev[4][4];
        {
            const float w0=cw[0],w1=cw[1],w2=cw[2],w3=cw[3],w4=cw[4],
                        w5=cw[5],w6=cw[6],w7=cw[7],w8=cw[8],cbb=cw[9];
            #pragma unroll
            for (int it = 0; it < 4; ++it) {
                int idx = tid + it*512;
                bool act = idx < R_*32;          // 62 rows x 32 col-quads
                int r  = (idx >> 5) + 1;         // 1..62
                int c0 = (idx & 31) * 4;
                float s = 0.f;
                if (act) {
                    float v6[3][6];
                    #pragma unroll
                    for (int dr = 0; dr < 3; ++dr) {
                        int rr = r - 1 + dr;
                        const float* ar = aa + rr*AS;
                        float4 mid = *(const float4*)&ar[c0];
                        v6[dr][1]=mid.x; v6[dr][2]=mid.y; v6[dr][3]=mid.z; v6[dr][4]=mid.w;
                        v6[dr][0] = (c0 > 0)   ? ar[c0-1] : aLR[rr];
                        v6[dr][5] = (c0 < 124) ? ar[c0+4] : aLR[64 + rr];
                    }
                    #pragma unroll
                    for (int j = 0; j < 4; ++j) {
                        float conv = cbb
                            + w0*v6[0][j] + w1*v6[0][j+1] + w2*v6[0][j+2]
                            + w3*v6[1][j] + w4*v6[1][j+1] + w5*v6[1][j+2]
                            + w6*v6[2][j] + w7*v6[2][j+1] + w8*v6[2][j+2];
                        float sig = __fdividef(1.f, 1.f + __expf(-conv));
                        float xx = fmaxf(v6[1][j+1] - sig, 0.f);
                        float e = __expf(xx) - 1.f;
                        ev[it][j] = e; s += e;
                    }
                } else {
                    ev[it][0]=ev[it][1]=ev[it][2]=ev[it][3]=0.f;
                }
                #pragma unroll
                for (int off = 16; off > 0; off >>= 1)
                    s += __shfl_down_sync(0xffffffffu, s, off);
                if (act && lane == 0) atomicAdd(&rowsum[r], s);
            }
        }
        __syncthreads();   // all conv reads of a done -> safe to overwrite with e

        // ---- write e planes (aliased over a) + zero halo rows 0/63 ----
        #pragma unroll
        for (int it = 0; it < 4; ++it) {
            int idx = tid + it*512;
            if (idx < R_*32) {
                int r  = (idx >> 5) + 1;
                int c0 = (idx & 31) * 4;
                uint2 hi, lo;
                hi.x = bfpack_hi(ev[it][0], ev[it][1]);
                hi.y = bfpack_hi(ev[it][2], ev[it][3]);
                lo.x = bfpack_lo(ev[it][0], ev[it][1]);
                lo.y = bfpack_lo(ev[it][2], ev[it][3]);
                *(uint2*)&ehi[r*ESB + c0] = hi;
                *(uint2*)&elo[r*ESB + c0] = lo;
            }
        }
        if (tid < 128) {
            int plane = tid >> 6, rsel = (tid >> 5) & 1, cq = tid & 31;
            __nv_bfloat16* ep = plane ? elo : ehi;
            int r = rsel ? 63 : 0;
            *(uint2*)&ep[r*ESB + cq*4] = make_uint2(0u, 0u);
        }
        __syncthreads();   // e ready

        // ---- PV via mma: pv += e[64][128] @ v[128][64] ----
        {
            const uint32_t vb2 = vU + p*V_BUF*2;
            const uint32_t eh0 = aeU, el0 = aeU + (AR*ESB)*2;
            #pragma unroll
            for (int kk = 0; kk < 8; ++kk) {
                const int k0 = kk*16;
                uint32_t ah[4], al[4];
                ldsm4(eh0 + ((rb+lr)*ESB + k0 + lc)*2, ah[0],ah[1],ah[2],ah[3]);
                ldsm4(el0 + ((rb+lr)*ESB + k0 + lc)*2, al[0],al[1],al[2],al[3]);
                uint32_t bh[4], bl[4];
                ldsm4t(vb2 + ((k0+lr)*VSB + hb + lc)*2, bh[0],bh[1],bh[2],bh[3]);
                ldsm4t(vb2 + (V_PLANE*2) + ((k0+lr)*VSB + hb + lc)*2,
                       bl[0],bl[1],bl[2],bl[3]);
                mma16816(pv[0], ah, bh[0], bh[1]);
                mma16816(pv[0], ah, bl[0], bl[1]);
                mma16816(pv[0], al, bh[0], bh[1]);
                mma16816(pv[1], ah, bh[2], bh[3]);
                mma16816(pv[1], ah, bl[2], bl[3]);
                mma16816(pv[1], al, bh[2], bh[3]);
            }
        }
        p ^= 1;
    }

    __syncthreads();       // rowsum complete (last chunk's atomics)

    // ---- normalize + store (per-warp tile, no reduction needed) ----
    #pragma unroll
    for (int half = 0; half < 2; ++half) {
        int ar = rb + cr + half*8;
        if (ar >= 1 && ar <= R_) {
            int gr = r0 + ar - 1;
            if (gr < N_) {
                float inv = __fdividef(1.f, rowsum[ar] + 1e-5f);
                #pragma unroll
                for (int nb = 0; nb < 2; ++nb) {
                    int col = hb + nb*8 + cc;
                    float2 o = make_float2(pv[nb][half*2+0]*inv,
                                           pv[nb][half*2+1]*inv);
                    *(float2*)&out[((size_t)(b*N_ + gr))*H_ + col] = o;
                }
            }
        }
    }
}

// ---------------------------------------------------------------------------
extern "C" void kernel_launch(void* const* d_in, const int* in_sizes, int n_in,
                              void* d_out, int out_size)
{
    const float* x  = (const float*)d_in[0];
    const float* Wq = (const float*)d_in[1];
    const float* bq = (const float*)d_in[2];
    const float* Wk = (const float*)d_in[3];
    const float* bk = (const float*)d_in[4];
    const float* Wv = (const float*)d_in[5];
    const float* bv = (const float*)d_in[6];
    const float* cw = (const float*)d_in[7];
    const float* cb = (const float*)d_in[8];
    float* out = (float*)d_out;

    qkv_kernel_75625784<<<dim3(512, 3), 256>>>(x, Wq, bq, Wk, bk, Wv, bv);

    const size_t smem_bytes =
        (size_t)AE_FLOATS*4                 // a / e aliased region
        + (size_t)2*AR*QSB*2                // qhi/qlo
        + (size_t)2*KT_BUF*2                // kt double buffer (hi+lo)
        + (size_t)2*V_BUF*2                 // v  double buffer (hi+lo)
        + (2*AR + AR + 16)*4;               // aLR, rowsum, cw
    cudaFuncSetAttribute(attn4_kernel_75625784,
                         cudaFuncAttributeMaxDynamicSharedMemorySize,
                         (int)smem_bytes);
    attn4_kernel_75625784<<<dim3(NT, B_), 512, smem_bytes>>>(cw, cb, out);
}